// round 1
// baseline (speedup 1.0000x reference)
#include <cuda_runtime.h>
#include <stdint.h>

// Loihi CUBA constants
#define AI 0.75f       // (4096-1024)/4096
#define AV 0.96875f    // (4096-128)/4096
#define TH 100.0f

// ---------------------------------------------------------------------------
// Bitpacked spike buffers: bit k of word j (of 4) = spike at t = j*32 + k.
// All buffers except g_s0 store the DELAYED stream (consumer always reads
// delayed spikes; the 128-bit <<1 is done at producer write time).
// ---------------------------------------------------------------------------
__device__ uint32_t g_s0[16 * 2  * 40 * 40 * 4];   // packed raw input spikes
__device__ uint32_t g_s1[16 * 8  * 40 * 40 * 4];   // conv1+LIF out (delayed)
__device__ uint32_t g_s2[16 * 8  * 20 * 20 * 4];   // pool1+LIF out (delayed)
__device__ uint32_t g_s3[16 * 16 * 20 * 20 * 4];   // conv2+LIF out (delayed)
__device__ uint32_t g_s4[16 * 16 * 10 * 10 * 4];   // pool2+LIF out (delayed)
__device__ uint32_t g_s5[16 * 3200 * 4];           // conv3+LIF out (delayed, fc layout)
__device__ float    g_x6[16 * 512 * 128];          // fc pre-activations

// ---------------------------------------------------------------------------
// K0: pack raw float spikes [16,2,40,40,128] (t contiguous) -> bit words
// ---------------------------------------------------------------------------
__global__ void k_pack(const float* __restrict__ sp) {
    int idx = blockIdx.x * blockDim.x + threadIdx.x;   // (n,c,h,w), 51200 total
    const float4* p = (const float4*)(sp + (size_t)idx * 128);
    uint32_t w[4];
#pragma unroll
    for (int j = 0; j < 4; j++) {
        uint32_t b = 0;
#pragma unroll
        for (int q = 0; q < 8; q++) {
            float4 v = p[j * 8 + q];
            b |= (v.x > 0.5f ? 1u : 0u) << (q * 4 + 0);
            b |= (v.y > 0.5f ? 1u : 0u) << (q * 4 + 1);
            b |= (v.z > 0.5f ? 1u : 0u) << (q * 4 + 2);
            b |= (v.w > 0.5f ? 1u : 0u) << (q * 4 + 3);
        }
        w[j] = b;
    }
    *((uint4*)&g_s0[(size_t)idx * 4]) = make_uint4(w[0], w[1], w[2], w[3]);
}

// ---------------------------------------------------------------------------
// K1: conv1 (2->8, 3x3, pad1, w*20) + LIF -> g_s1 (delayed)
// grid = 16n * 40h ; block = 40w * 8o = 320 threads
// ---------------------------------------------------------------------------
__global__ void k_conv1(const float* __restrict__ cw) {
    __shared__ uint32_t sh[2 * 3 * 42 * 4];  // [c][dy][wx(42, halo)][j]
    int b = blockIdx.x;
    int n = b / 40, h = b % 40;
    int tid = threadIdx.x;

    for (int i = tid; i < 2 * 3 * 42 * 4; i += 320) {
        int j = i & 3;
        int t2 = i >> 2;
        int wx = t2 % 42;
        int t3 = t2 / 42;
        int dy = t3 % 3;
        int c  = t3 / 3;
        int r = h - 1 + dy, ws = wx - 1;
        uint32_t v = 0;
        if (r >= 0 && r < 40 && ws >= 0 && ws < 40)
            v = g_s0[(((n * 2 + c) * 40 + r) * 40 + ws) * 4 + j];
        sh[i] = v;
    }
    __syncthreads();

    int w = tid % 40, o = tid / 40;
    float wg[18];
#pragma unroll
    for (int i = 0; i < 18; i++) wg[i] = cw[o * 18 + i] * 20.0f;

    float u = 0.f, v = 0.f;
    uint32_t ow[4];
#pragma unroll
    for (int j = 0; j < 4; j++) {
        float acc[32];
#pragma unroll
        for (int k = 0; k < 32; k++) acc[k] = 0.f;
#pragma unroll
        for (int c = 0; c < 2; c++)
#pragma unroll
        for (int dy = 0; dy < 3; dy++)
#pragma unroll
        for (int dx = 0; dx < 3; dx++) {
            uint32_t wd = sh[(((c * 3 + dy) * 42) + (w + dx)) * 4 + j];
            float wt = wg[c * 9 + dy * 3 + dx];
#pragma unroll
            for (int k = 0; k < 32; k++)
                if (wd & (1u << k)) acc[k] += wt;
        }
        uint32_t bits = 0;
#pragma unroll
        for (int k = 0; k < 32; k++) {
            u = AI * u + acc[k];
            v = AV * v + u;
            if (v >= TH) { bits |= 1u << k; v = 0.f; }
        }
        ow[j] = bits;
    }
    uint32_t d0 = ow[0] << 1;
    uint32_t d1 = (ow[1] << 1) | (ow[0] >> 31);
    uint32_t d2 = (ow[2] << 1) | (ow[1] >> 31);
    uint32_t d3 = (ow[3] << 1) | (ow[2] >> 31);
    *((uint4*)&g_s1[((((n * 8 + o) * 40 + h) * 40 + w)) * 4]) = make_uint4(d0, d1, d2, d3);
}

// ---------------------------------------------------------------------------
// K2: 2x2 sum pool (* pool_w scalar) + LIF -> out (delayed). Generic.
// ---------------------------------------------------------------------------
__global__ void k_pool(const uint32_t* __restrict__ in, uint32_t* __restrict__ out,
                       int C, int Hin, const float* __restrict__ pw) {
    int Ho = Hin / 2;
    int idx = blockIdx.x * blockDim.x + threadIdx.x;   // (n,c,ph,pw)
    int pwi = idx % Ho;
    int t = idx / Ho;
    int phi = t % Ho; t /= Ho;
    int c = t % C;
    int n = t / C;
    float scale = pw[0];

    const uint32_t* b00 = &in[((((n * C + c) * Hin + 2 * phi) * Hin) + 2 * pwi) * 4];
    const uint32_t* b10 = b00 + Hin * 4;

    float u = 0.f, v = 0.f;
    uint32_t ow[4];
#pragma unroll
    for (int j = 0; j < 4; j++) {
        uint32_t a = b00[j], bb = b00[4 + j], cc = b10[j], d = b10[4 + j];
        uint32_t bits = 0;
#pragma unroll
        for (int k = 0; k < 32; k++) {
            int cnt = (int)((a >> k) & 1u) + (int)((bb >> k) & 1u)
                    + (int)((cc >> k) & 1u) + (int)((d >> k) & 1u);
            float x = (float)cnt * scale;
            u = AI * u + x;
            v = AV * v + u;
            if (v >= TH) { bits |= 1u << k; v = 0.f; }
        }
        ow[j] = bits;
    }
    uint32_t d0 = ow[0] << 1;
    uint32_t d1 = (ow[1] << 1) | (ow[0] >> 31);
    uint32_t d2 = (ow[2] << 1) | (ow[1] >> 31);
    uint32_t d3 = (ow[3] << 1) | (ow[2] >> 31);
    *((uint4*)&out[(size_t)idx * 4]) = make_uint4(d0, d1, d2, d3);
}

// ---------------------------------------------------------------------------
// K3/K5: generic 3x3 conv (pad 1) on bitpacked spikes + LIF -> out (delayed).
// Whole input image for one n lives (zero-padded) in shared memory.
// grid = (Cout/OPB, 16n) ; block = OPB * H * H threads.
// ---------------------------------------------------------------------------
template <int CIN, int H, int OPB>
__global__ void k_conv(const uint32_t* __restrict__ in, uint32_t* __restrict__ out,
                       const float* __restrict__ wsrc, float wscale, int Cout) {
    constexpr int PH = H + 2;
    constexpr int INW = CIN * PH * PH * 4;
    extern __shared__ uint32_t sh[];
    float* shw = (float*)&sh[INW];  // OPB*CIN*9 scaled weights

    int og = blockIdx.x, n = blockIdx.y;
    int tid = threadIdx.x;
    int nth = blockDim.x;

    for (int i = tid; i < INW; i += nth) sh[i] = 0u;
    __syncthreads();
    for (int i = tid; i < CIN * H * H * 4; i += nth) {
        int j = i & 3;
        int t = i >> 2;
        int w = t % H; t /= H;
        int h = t % H;
        int c = t / H;
        sh[(((c * PH + h + 1) * PH) + (w + 1)) * 4 + j] =
            in[(((n * CIN + c) * H * H) + h * H + w) * 4 + j];
    }
    for (int i = tid; i < OPB * CIN * 9; i += nth)
        shw[i] = wsrc[og * OPB * CIN * 9 + i] * wscale;
    __syncthreads();

    int w = tid % H;
    int h = (tid / H) % H;
    int ol = tid / (H * H);

    float u = 0.f, v = 0.f;
    uint32_t ow[4];
#pragma unroll
    for (int j = 0; j < 4; j++) {
        float acc[32];
#pragma unroll
        for (int k = 0; k < 32; k++) acc[k] = 0.f;
        for (int c = 0; c < CIN; c++) {
            const uint32_t* base = &sh[((c * PH + h) * PH + w) * 4 + j];
            const float* wp = &shw[(ol * CIN + c) * 9];
#pragma unroll
            for (int dy = 0; dy < 3; dy++)
#pragma unroll
            for (int dx = 0; dx < 3; dx++) {
                uint32_t wd = base[(dy * PH + dx) * 4];
                float wt = wp[dy * 3 + dx];
#pragma unroll
                for (int k = 0; k < 32; k++)
                    if (wd & (1u << k)) acc[k] += wt;
            }
        }
        uint32_t bits = 0;
#pragma unroll
        for (int k = 0; k < 32; k++) {
            u = AI * u + acc[k];
            v = AV * v + u;
            if (v >= TH) { bits |= 1u << k; v = 0.f; }
        }
        ow[j] = bits;
    }
    int o = og * OPB + ol;
    uint32_t d0 = ow[0] << 1;
    uint32_t d1 = (ow[1] << 1) | (ow[0] >> 31);
    uint32_t d2 = (ow[2] << 1) | (ow[1] >> 31);
    uint32_t d3 = (ow[3] << 1) | (ow[2] >> 31);
    *((uint4*)&out[(((n * Cout + o) * H * H) + h * H + w) * 4]) = make_uint4(d0, d1, d2, d3);
}

// ---------------------------------------------------------------------------
// K6: fc pre-activation x6[n,o,t] = sum_c W[o,c] * bit(s5d[n,c], t)
// grid = (8 o-blocks of 64, 16 n); block = 256 threads = (64 o) x (4 t-words)
// ---------------------------------------------------------------------------
__global__ void k_fc(const uint32_t* __restrict__ bits, const float* __restrict__ W,
                     float* __restrict__ x6) {
    __shared__ float    shw[64][129];   // +1 pad: conflict-free reads across o
    __shared__ uint32_t shb[128 * 4];   // 128 c x 4 words

    int ob = blockIdx.x, n = blockIdx.y;
    int tid = threadIdx.x;
    int ol = tid >> 2;      // 0..63
    int j  = tid & 3;       // 0..3

    float acc[32];
#pragma unroll
    for (int k = 0; k < 32; k++) acc[k] = 0.f;

    for (int cb = 0; cb < 3200; cb += 128) {
        __syncthreads();
        // load W chunk [64 o][128 c]: each thread 32 contiguous c of one o row
        {
            int oo = tid >> 2;
            int cofs = (tid & 3) * 32;
            const float4* wp4 = (const float4*)&W[(size_t)(ob * 64 + oo) * 3200 + cb + cofs];
#pragma unroll
            for (int s = 0; s < 8; s++) {
                float4 vv = wp4[s];
                shw[oo][cofs + 4 * s + 0] = vv.x;
                shw[oo][cofs + 4 * s + 1] = vv.y;
                shw[oo][cofs + 4 * s + 2] = vv.z;
                shw[oo][cofs + 4 * s + 3] = vv.w;
            }
        }
        // load bit words for this chunk
        for (int i = tid; i < 512; i += 256)
            shb[i] = bits[(size_t)(n * 3200 + cb + (i >> 2)) * 4 + (i & 3)];
        __syncthreads();

#pragma unroll 4
        for (int c = 0; c < 128; c++) {
            uint32_t wd = shb[c * 4 + j];
            float wt = shw[ol][c];
#pragma unroll
            for (int k = 0; k < 32; k++)
                if (wd & (1u << k)) acc[k] += wt;
        }
    }

    float* xp = &x6[((size_t)(n * 512 + ob * 64 + ol) * 128) + j * 32];
#pragma unroll
    for (int k = 0; k < 32; k++) xp[k] = acc[k];
}

// ---------------------------------------------------------------------------
// K7: final LIF over x6 + output delay-shift -> d_out [16,512,1,1,128] float
// ---------------------------------------------------------------------------
__global__ void k_lif_out(const float* __restrict__ x6, float* __restrict__ out) {
    int idx = blockIdx.x * blockDim.x + threadIdx.x;   // (n,o), 8192 total
    const float* xp = &x6[(size_t)idx * 128];
    float* op = &out[(size_t)idx * 128];
    float u = 0.f, v = 0.f, prev = 0.f;
#pragma unroll 8
    for (int t = 0; t < 128; t++) {
        op[t] = prev;
        u = AI * u + xp[t];
        v = AV * v + u;
        if (v >= TH) { prev = 1.f; v = 0.f; } else { prev = 0.f; }
    }
}

// ---------------------------------------------------------------------------
extern "C" void kernel_launch(void* const* d_in, const int* in_sizes, int n_in,
                              void* d_out, int out_size) {
    const float* spike = (const float*)d_in[0];
    const float* c1w   = (const float*)d_in[1];
    const float* c2w   = (const float*)d_in[2];
    const float* c3w   = (const float*)d_in[3];
    const float* p1w   = (const float*)d_in[4];
    const float* p2w   = (const float*)d_in[5];
    const float* fcw   = (const float*)d_in[6];
    float* out = (float*)d_out;

    uint32_t *s1, *s2, *s3, *s4, *s5;
    float* x6;
    cudaGetSymbolAddress((void**)&s1, g_s1);
    cudaGetSymbolAddress((void**)&s2, g_s2);
    cudaGetSymbolAddress((void**)&s3, g_s3);
    cudaGetSymbolAddress((void**)&s4, g_s4);
    cudaGetSymbolAddress((void**)&s5, g_s5);
    cudaGetSymbolAddress((void**)&x6, g_x6);

    // conv2 needs ~62.5KB dynamic shared
    static_assert(8 * 22 * 22 * 4 * 4 + 2 * 8 * 9 * 4 == 62528, "smem");
    cudaFuncSetAttribute((const void*)k_conv<8, 20, 2>,
                         cudaFuncAttributeMaxDynamicSharedMemorySize, 65536);
    cudaFuncSetAttribute((const void*)k_conv<16, 10, 8>,
                         cudaFuncAttributeMaxDynamicSharedMemorySize, 49152);

    k_pack<<<200, 256>>>(spike);                                   // 51200 neurons
    k_conv1<<<640, 320>>>(c1w);                                    // -> g_s1 (delayed)
    k_pool<<<200, 256>>>(s1, s2, 8, 40, p1w);                      // -> g_s2 (delayed)
    k_conv<8, 20, 2><<<dim3(8, 16), 800, 62528>>>(s2, s3, c2w, 100.0f, 16);
    k_pool<<<100, 256>>>(s3, s4, 16, 20, p2w);                     // -> g_s4 (delayed)
    k_conv<16, 10, 8><<<dim3(4, 16), 800, 41472>>>(s4, s5, c3w, 100.0f, 32);
    k_fc<<<dim3(8, 16), 256>>>(s5, fcw, x6);
    k_lif_out<<<32, 256>>>(x6, out);
}